// round 3
// baseline (speedup 1.0000x reference)
#include <cuda_runtime.h>
#include <cuda_bf16.h>
#include <cstdint>

// upfirdn2d, UP=1, DOWN=2, PAD=5, separable sym6 (12 taps).
// y[i,j] = sum_{p,q} h[p]*h[q] * x[2i+6-p, 2j+6-q]  (x zero-padded outside [0,256))
// Rewritten with k = 11-p: y[i,j] = sum_k HR[k] * tmp[2i+k][j],
//   tmp[r][j] = sum_k HR[k] * x[r][2j+k-5],  HR[k] = h[11-k].

#define TILE     32      // output tile (rows == cols)
#define IN_ROWS  74      // 2*32 + 12 - 2  halo rows
#define IN_W     76      // 74 cols needed, padded to 76 for aligned float4
#define IMG_H    256
#define IMG_W    256
#define OUT_H    128
#define OUT_W    128

__constant__ float HR[12] = {
     0.015404109327027373f,
     0.0034907120842174702f,
    -0.11799011114819057f,
    -0.048311742585633f,
     0.4910559419267466f,
     0.787641141030194f,
     0.3379294217276218f,
    -0.07263752278646252f,
    -0.021060292512300564f,
     0.04472490177066578f,
     0.0017677118642428036f,
    -0.007800708325034148f
};

__global__ void __launch_bounds__(256)
hp_sym6_down2_kernel(const float* __restrict__ in, float* __restrict__ out)
{
    __shared__ float s_in[IN_ROWS][IN_W];     // 74*76*4 = 22496 B
    __shared__ float s_tmp[IN_ROWS][TILE];    // 74*32*4 =  9472 B

    const int img  = blockIdx.z;
    const int i0   = blockIdx.y * TILE;       // first output row of tile
    const int j0   = blockIdx.x * TILE;       // first output col of tile
    const int tid  = threadIdx.x;

    const float* __restrict__ src = in + (size_t)img * (IMG_H * IMG_W);
    const int rowBase = 2 * i0 - 5;           // global row of s_in row 0
    const int colBase = 2 * j0 - 5;           // global col of s_in col 0

    // ---- Stage 1: load halo tile (zero outside image). Incremental row/col
    //      walk: tid covers {r = idx / IN_W, c = idx % IN_W} for
    //      idx = tid, tid+256, ... ; step of 256 = +3 rows, +28 cols (mod 76).
    {
        int r = tid / IN_W;
        int c = tid - r * IN_W;
        #pragma unroll 1
        for (int idx = tid; idx < IN_ROWS * IN_W; idx += 256) {
            int gr = rowBase + r;
            int gc = colBase + c;
            float v = 0.0f;
            if ((unsigned)gr < (unsigned)IMG_H && (unsigned)gc < (unsigned)IMG_W)
                v = src[gr * IMG_W + gc];
            s_in[r][c] = v;
            r += 3; c += 28;
            if (c >= IN_W) { c -= IN_W; r += 1; }
        }
    }
    __syncthreads();

    // ---- Stage 2: horizontal 12-tap, stride 2. 4 outputs per thread via
    //      aligned float4 shared loads: quad q covers oj = 4q..4q+3, needing
    //      s_in[r][8q .. 8q+17]  (<= col 75, inside padded width). ----
    for (int idx = tid; idx < IN_ROWS * 8; idx += 256) {
        int r = idx >> 3;
        int q = idx & 7;
        const float4* row4 = reinterpret_cast<const float4*>(&s_in[r][0]);
        float4 v0 = row4[q * 2 + 0];
        float4 v1 = row4[q * 2 + 1];
        float4 v2 = row4[q * 2 + 2];
        float4 v3 = row4[q * 2 + 3];
        float4 v4 = row4[q * 2 + 4];
        float w[20] = { v0.x, v0.y, v0.z, v0.w,
                        v1.x, v1.y, v1.z, v1.w,
                        v2.x, v2.y, v2.z, v2.w,
                        v3.x, v3.y, v3.z, v3.w,
                        v4.x, v4.y, v4.z, v4.w };
        #pragma unroll
        for (int m = 0; m < 4; m++) {
            float acc = 0.0f;
            #pragma unroll
            for (int k = 0; k < 12; k++)
                acc = fmaf(HR[k], w[2 * m + k], acc);
            s_tmp[r][q * 4 + m] = acc;
        }
    }
    __syncthreads();

    // ---- Stage 3: vertical 12-tap, stride 2, register strip reuse.
    //      thread = (g, oj): g in 0..7 owns output rows 4g..4g+3, which read
    //      tmp rows 8g .. 8g+17 (18 rows, loaded once). ----
    {
        const int oj = tid & 31;
        const int g  = tid >> 5;
        float t[18];
        #pragma unroll
        for (int r = 0; r < 18; r++)
            t[r] = s_tmp[8 * g + r][oj];

        float* __restrict__ dst = out + (size_t)img * (OUT_H * OUT_W);
        #pragma unroll
        for (int m = 0; m < 4; m++) {
            float acc = 0.0f;
            #pragma unroll
            for (int k = 0; k < 12; k++)
                acc = fmaf(HR[k], t[2 * m + k], acc);
            int oi = 4 * g + m;
            dst[(i0 + oi) * OUT_W + (j0 + oj)] = acc;
        }
    }
}

extern "C" void kernel_launch(void* const* d_in, const int* in_sizes, int n_in,
                              void* d_out, int out_size)
{
    const float* x = (const float*)d_in[0];
    float* y = (float*)d_out;

    int n_img = in_sizes[0] / (IMG_H * IMG_W);   // 16*64 = 1024
    dim3 grid(OUT_W / TILE, OUT_H / TILE, n_img); // (4, 4, 1024)
    dim3 block(256);
    hp_sym6_down2_kernel<<<grid, block>>>(x, y);
}

// round 4
// speedup vs baseline: 2.6601x; 2.6601x over previous
#include <cuda_runtime.h>
#include <cstdint>

// upfirdn2d, UP=1, DOWN=2, PAD=5, separable sym6 (12 taps), fp32.
// y[i,j] = sum_{p,q} HR[p]*HR[q] * x[2i+p-5, 2j+q-5], HR[k] = h[11-k], x zero-padded.
// Vertical-first: tmpV[i][c] = sum_p HR[p] x[2i+p-5][c]   (coalesced global reads)
// then horizontal: y[i][j]   = sum_q HR[q] tmpV[i][2j+q-5] (smem window reads)

#define IMG_H   256
#define IMG_W   256
#define OUT_H   128
#define OUT_W   128
#define O_ROWS  64            // output rows per CTA (full 128-col width)
#define STRIDE  276           // tmpV row stride in floats (276 % 32 = 20 -> low LDS conflict)
#define PAD     8             // left zero pad inside tmpV row; data words [8, 264)
#define NT      512

// sym6 reconstruction low-pass, reversed (HR[k] = h[11-k]) — compile-time
// constants so ptxas emits immediate-form FFMA (rt_SMSP=1, 2x throughput).
#define HR0  ( 0.015404109327027373f)
#define HR1  ( 0.0034907120842174702f)
#define HR2  (-0.11799011114819057f)
#define HR3  (-0.048311742585633f)
#define HR4  ( 0.4910559419267466f)
#define HR5  ( 0.787641141030194f)
#define HR6  ( 0.3379294217276218f)
#define HR7  (-0.07263752278646252f)
#define HR8  (-0.021060292512300564f)
#define HR9  ( 0.04472490177066578f)
#define HR10 ( 0.0017677118642428036f)
#define HR11 (-0.007800708325034148f)

__device__ __forceinline__ float tap12(const float* w) {
    float a;
    a = HR0 * w[0];
    a = fmaf(HR1,  w[1],  a);
    a = fmaf(HR2,  w[2],  a);
    a = fmaf(HR3,  w[3],  a);
    a = fmaf(HR4,  w[4],  a);
    a = fmaf(HR5,  w[5],  a);
    a = fmaf(HR6,  w[6],  a);
    a = fmaf(HR7,  w[7],  a);
    a = fmaf(HR8,  w[8],  a);
    a = fmaf(HR9,  w[9],  a);
    a = fmaf(HR10, w[10], a);
    a = fmaf(HR11, w[11], a);
    return a;
}

__global__ void __launch_bounds__(NT, 3)
hp_sym6_v2(const float* __restrict__ in, float* __restrict__ out)
{
    extern __shared__ float tmpV[];   // [O_ROWS][STRIDE]

    const int img = blockIdx.x;
    const int ty  = blockIdx.y;       // 0..1
    const int tid = threadIdx.x;
    const int i0  = ty * O_ROWS;      // first output row of this CTA

    const float* __restrict__ src = in + (size_t)img * (IMG_H * IMG_W);

    // ---- zero the pad columns of tmpV (words [0,8) and [264,276) per row) ----
    #pragma unroll
    for (int z = tid; z < O_ROWS * 20; z += NT) {
        int rr = z / 20;
        int pz = z - rr * 20;
        tmpV[rr * STRIDE + (pz < 8 ? pz : 256 + pz)] = 0.0f;
    }

    // ---- Phase V: vertical 12-tap, stride 2, straight from global ----
    // thread -> (column c, half h). Each thread: 32 output rows of one column,
    // rolling 12-register window, 74 coalesced scalar loads.
    {
        const int c  = tid & 255;         // 0..255
        const int h  = tid >> 8;          // 0..1
        const int ir0 = i0 + h * 32;      // first out row of this strip
        const int g0  = 2 * ir0 - 5;      // first input row needed
        const float* __restrict__ colp = src + c;

        float w[12];
        #pragma unroll
        for (int t = 0; t < 10; t++) {
            int g = g0 + t;
            w[t] = ((unsigned)g < (unsigned)IMG_H) ? colp[g * IMG_W] : 0.0f;
        }

        float* sdst = &tmpV[(h * 32) * STRIDE + PAD + c];
        #pragma unroll
        for (int i = 0; i < 32; i++) {
            int gA = g0 + 2 * i + 10;
            int gB = gA + 1;
            w[10] = ((unsigned)gA < (unsigned)IMG_H) ? colp[gA * IMG_W] : 0.0f;
            w[11] = ((unsigned)gB < (unsigned)IMG_H) ? colp[gB * IMG_W] : 0.0f;

            sdst[i * STRIDE] = tap12(w);

            #pragma unroll
            for (int k = 0; k < 10; k++) w[k] = w[k + 2];
        }
    }
    __syncthreads();

    // ---- Phase H: horizontal 12-tap, stride 2, from smem; 16 outputs/thread ----
    // warp covers 4 rows x 8 col-groups; lane = (c8 = lane>>2, isub = lane&3)
    // so each smem phase mixes rows -> <=2-way bank conflicts with STRIDE=276.
    {
        const int wid  = tid >> 5;
        const int lane = tid & 31;
        const int c8   = lane >> 2;       // 0..7  (16 output cols each)
        const int isub = lane & 3;
        const int il   = 4 * wid + isub;  // local output row 0..63

        // window words [32*c8, 32*c8+48) of row il cover needed [32*c8+3, 32*c8+44]
        const float* rowv = &tmpV[il * STRIDE + 32 * c8];
        float v[48];
        #pragma unroll
        for (int m = 0; m < 12; m++) {
            float4 q = *reinterpret_cast<const float4*>(rowv + 4 * m);
            v[4 * m + 0] = q.x;
            v[4 * m + 1] = q.y;
            v[4 * m + 2] = q.z;
            v[4 * m + 3] = q.w;
        }

        float o[16];
        #pragma unroll
        for (int d = 0; d < 16; d++)
            o[d] = tap12(&v[2 * d + 3]);

        float* __restrict__ dst =
            out + (size_t)img * (OUT_H * OUT_W) + (i0 + il) * OUT_W + 16 * c8;
        #pragma unroll
        for (int s = 0; s < 4; s++) {
            float4 q = make_float4(o[4*s], o[4*s+1], o[4*s+2], o[4*s+3]);
            *reinterpret_cast<float4*>(dst + 4 * s) = q;
        }
    }
}

extern "C" void kernel_launch(void* const* d_in, const int* in_sizes, int n_in,
                              void* d_out, int out_size)
{
    const float* x = (const float*)d_in[0];
    float* y = (float*)d_out;

    int n_img = in_sizes[0] / (IMG_H * IMG_W);      // 1024
    size_t smem = (size_t)O_ROWS * STRIDE * sizeof(float);   // 70656 B

    cudaFuncSetAttribute(hp_sym6_v2,
                         cudaFuncAttributeMaxDynamicSharedMemorySize, (int)smem);

    dim3 grid(n_img, OUT_H / O_ROWS);   // (1024, 2)
    hp_sym6_v2<<<grid, NT, smem>>>(x, y);
}

// round 5
// speedup vs baseline: 3.3049x; 1.2424x over previous
#include <cuda_runtime.h>
#include <cstdint>

// upfirdn2d, UP=1, DOWN=2, PAD=5, separable sym6 (12 taps), fp32.
// Vertical-first from global (coalesced float2 column strips, register ring),
// horizontal from smem. y[i,j] = sum_q HR[q] * tmpV[i][2j+q-5].

#define IMG_H   256
#define IMG_W   256
#define OUT_H   128
#define OUT_W   128
#define O_ROWS  64
#define STRIDE  276           // floats; 276 % 32 = 20 -> conflict-free phase H
#define PADL    8             // left zero pad; data words [8, 264)
#define NT      512

#define HR0  ( 0.015404109327027373f)
#define HR1  ( 0.0034907120842174702f)
#define HR2  (-0.11799011114819057f)
#define HR3  (-0.048311742585633f)
#define HR4  ( 0.4910559419267466f)
#define HR5  ( 0.787641141030194f)
#define HR6  ( 0.3379294217276218f)
#define HR7  (-0.07263752278646252f)
#define HR8  (-0.021060292512300564f)
#define HR9  ( 0.04472490177066578f)
#define HR10 ( 0.0017677118642428036f)
#define HR11 (-0.007800708325034148f)

__device__ __forceinline__ float tap12(const float* w) {
    float a;
    a = HR0 * w[0];
    a = fmaf(HR1,  w[1],  a);
    a = fmaf(HR2,  w[2],  a);
    a = fmaf(HR3,  w[3],  a);
    a = fmaf(HR4,  w[4],  a);
    a = fmaf(HR5,  w[5],  a);
    a = fmaf(HR6,  w[6],  a);
    a = fmaf(HR7,  w[7],  a);
    a = fmaf(HR8,  w[8],  a);
    a = fmaf(HR9,  w[9],  a);
    a = fmaf(HR10, w[10], a);
    a = fmaf(HR11, w[11], a);
    return a;
}

__device__ __forceinline__ float2 tap12v(const float2* w) {
    float2 a;
    a.x = HR0 * w[0].x;            a.y = HR0 * w[0].y;
    a.x = fmaf(HR1,  w[1].x, a.x); a.y = fmaf(HR1,  w[1].y, a.y);
    a.x = fmaf(HR2,  w[2].x, a.x); a.y = fmaf(HR2,  w[2].y, a.y);
    a.x = fmaf(HR3,  w[3].x, a.x); a.y = fmaf(HR3,  w[3].y, a.y);
    a.x = fmaf(HR4,  w[4].x, a.x); a.y = fmaf(HR4,  w[4].y, a.y);
    a.x = fmaf(HR5,  w[5].x, a.x); a.y = fmaf(HR5,  w[5].y, a.y);
    a.x = fmaf(HR6,  w[6].x, a.x); a.y = fmaf(HR6,  w[6].y, a.y);
    a.x = fmaf(HR7,  w[7].x, a.x); a.y = fmaf(HR7,  w[7].y, a.y);
    a.x = fmaf(HR8,  w[8].x, a.x); a.y = fmaf(HR8,  w[8].y, a.y);
    a.x = fmaf(HR9,  w[9].x, a.x); a.y = fmaf(HR9,  w[9].y, a.y);
    a.x = fmaf(HR10, w[10].x, a.x); a.y = fmaf(HR10, w[10].y, a.y);
    a.x = fmaf(HR11, w[11].x, a.x); a.y = fmaf(HR11, w[11].y, a.y);
    return a;
}

// Vertical pass for one 16-output-row strip of 2 columns.
// CHECK=false: all 42 input rows in range -> raw loads, no predicates.
template<bool CHECK>
__device__ __forceinline__ void vpass(const float2* __restrict__ colp,
                                      float* __restrict__ sdst, int g0)
{
    float2 w[12];
    #pragma unroll
    for (int t = 0; t < 10; t++) {
        int g = g0 + t;
        if (CHECK && (unsigned)g >= (unsigned)IMG_H) w[t] = make_float2(0.f, 0.f);
        else                                         w[t] = __ldg(colp + g * (IMG_W / 2));
    }
    #pragma unroll
    for (int i = 0; i < 16; i++) {
        int gA = g0 + 2 * i + 10;
        int gB = gA + 1;
        if (CHECK && (unsigned)gA >= (unsigned)IMG_H) w[10] = make_float2(0.f, 0.f);
        else                                          w[10] = __ldg(colp + gA * (IMG_W / 2));
        if (CHECK && (unsigned)gB >= (unsigned)IMG_H) w[11] = make_float2(0.f, 0.f);
        else                                          w[11] = __ldg(colp + gB * (IMG_W / 2));

        float2 o = tap12v(w);
        *reinterpret_cast<float2*>(sdst + i * STRIDE) = o;

        #pragma unroll
        for (int k = 0; k < 10; k++) w[k] = w[k + 2];
    }
}

__global__ void __launch_bounds__(NT, 2)
hp_sym6_v3(const float* __restrict__ in, float* __restrict__ out)
{
    extern __shared__ float tmpV[];   // [O_ROWS][STRIDE]

    const int ty  = blockIdx.x;       // tile within image (fastest -> L2 halo reuse)
    const int img = blockIdx.y;
    const int tid = threadIdx.x;
    const int i0  = ty * O_ROWS;

    const float* __restrict__ src = in + (size_t)img * (IMG_H * IMG_W);

    // zero pad columns: words [0,8) and [264,276) of each tmpV row
    #pragma unroll
    for (int z = tid; z < O_ROWS * 20; z += NT) {
        int rr = z / 20;
        int pz = z - rr * 20;
        tmpV[rr * STRIDE + (pz < 8 ? pz : 256 + pz)] = 0.0f;
    }

    // ---- Phase V: 4 strips x 16 output rows, 2 columns (float2) per thread ----
    {
        const int h  = tid >> 7;            // strip 0..3
        const int c2 = (tid & 127) * 2;     // column pair
        const int g0 = 2 * (i0 + h * 16) - 5;
        const float2* colp = reinterpret_cast<const float2*>(src + c2);
        float* sdst = &tmpV[(h * 16) * STRIDE + PADL + c2];

        if (g0 >= 0 && g0 + 41 < IMG_H) vpass<false>(colp, sdst, g0);
        else                            vpass<true >(colp, sdst, g0);
    }
    __syncthreads();

    // ---- Phase H: 12-tap stride-2 from smem, 16 outputs per thread ----
    {
        const int wid  = tid >> 5;          // 0..15
        const int lane = tid & 31;
        const int c8   = lane >> 2;         // 0..7 -> 16 output cols each
        const int isub = lane & 3;
        const int il   = 4 * wid + isub;    // local output row 0..63

        const float* rowv = &tmpV[il * STRIDE + 32 * c8];
        float v[48];
        #pragma unroll
        for (int m = 0; m < 12; m++) {
            float4 q = *reinterpret_cast<const float4*>(rowv + 4 * m);
            v[4 * m + 0] = q.x;
            v[4 * m + 1] = q.y;
            v[4 * m + 2] = q.z;
            v[4 * m + 3] = q.w;
        }

        float o[16];
        #pragma unroll
        for (int d = 0; d < 16; d++)
            o[d] = tap12(&v[2 * d + 3]);

        float* __restrict__ dst =
            out + (size_t)img * (OUT_H * OUT_W) + (i0 + il) * OUT_W + 16 * c8;
        #pragma unroll
        for (int s = 0; s < 4; s++) {
            float4 q = make_float4(o[4*s], o[4*s+1], o[4*s+2], o[4*s+3]);
            *reinterpret_cast<float4*>(dst + 4 * s) = q;
        }
    }
}

extern "C" void kernel_launch(void* const* d_in, const int* in_sizes, int n_in,
                              void* d_out, int out_size)
{
    const float* x = (const float*)d_in[0];
    float* y = (float*)d_out;

    int n_img = in_sizes[0] / (IMG_H * IMG_W);            // 1024
    size_t smem = (size_t)O_ROWS * STRIDE * sizeof(float); // 70656 B

    cudaFuncSetAttribute(hp_sym6_v3,
                         cudaFuncAttributeMaxDynamicSharedMemorySize, (int)smem);

    dim3 grid(OUT_H / O_ROWS, n_img);   // (2, 1024): tiles fastest for L2 reuse
    hp_sym6_v3<<<grid, NT, smem>>>(x, y);
}